// round 6
// baseline (speedup 1.0000x reference)
#include <cuda_runtime.h>
#include <cuda_bf16.h>
#include <math.h>

// Problem constants
#define Bb 2
#define Hh 8
#define Ss 2048
#define Dd 64
#define MASK_FILL -1e9f
#define SCALE 0.08838834764831845f   // 1/sqrt(2*D)

#define OUT_ELEMS (Bb*Hh*Ss*Dd)            // 2,097,152
#define P_ELEMS   ((size_t)Bb*Hh*Ss*Ss)    // 67,108,864
#define NROWS     (Bb*Hh*Ss)               // 32,768
#define SMS 66    // smem row stride (floats): even -> 8B rows; 66 mod 32 = 2 -> conflict-free b-loads

// ---- scratch (__device__ globals: alloc-free rule) ----
__device__ float g_rmax[NROWS];
__device__ float g_rinv[NROWS];
__device__ float g_scr_fallback[P_ELEMS];   // used only if d_out lacks the p region

// packed fp32x2 FMA (SASS FFMA2) — PTX-only form (see SASS_QUICKREF: ptxas
// never auto-fuses; fma.rn.f32x2 is the sanctioned route)
__device__ __forceinline__ unsigned long long fma_f32x2(
    unsigned long long a, unsigned long long b, unsigned long long c)
{
    unsigned long long d;
    asm("fma.rn.f32x2 %0, %1, %2, %3;" : "=l"(d) : "l"(a), "l"(b), "l"(c));
    return d;
}
__device__ __forceinline__ float f32x2_sum(unsigned long long v)
{
    float lo, hi;
    asm("mov.b64 {%0, %1}, %2;" : "=f"(lo), "=f"(hi) : "l"(v));
    return lo + hi;
}

// ---------------------------------------------------------------------------
// Kernel 1: q-strip scores + fused online softmax stats.
// Block = 64 q-rows of one (b,h); loops over 32 k-tiles of 64.
// Double-buffered Ks, one __syncthreads per tile:
//   sync -> LDG(next K, cur pos/mask) -> GEMM(Ks[buf]) -> STS(Ks[buf^1]) -> epilogue
// grid = (S/64, B*H), block = 256 (rows ty+16i, cols tx+16j)
// ---------------------------------------------------------------------------
__global__ __launch_bounds__(256, 2)
void scores_stats_kernel(const float* __restrict__ Q,
                         const float* __restrict__ K,
                         const float* __restrict__ pos,
                         const int*   __restrict__ mask,
                         float* __restrict__ scr)
{
    __shared__ float Qs[64 * SMS];
    __shared__ float Ks[2][64 * SMS];

    const int bh = blockIdx.y;
    const int b  = bh >> 3;                 // H = 8
    const int q0 = blockIdx.x * 64;
    const int tid = threadIdx.x;
    const int tx = tid & 15;
    const int ty = tid >> 4;
    const int lr  = tid >> 4;               // loader rows lr+16*it
    const int lc4 = (tid & 15) * 4;         // loader col*4

    // ---- Q strip once: [row][k] ----
    const float* Qg = Q + ((size_t)bh * Ss + q0) * Dd;
    #pragma unroll
    for (int it = 0; it < 4; it++) {
        const int r = lr + it * 16;
        float4 v = *(const float4*)(Qg + r * Dd + lc4);
        *(float2*)&Qs[r * SMS + lc4]     = make_float2(v.x, v.y);
        *(float2*)&Qs[r * SMS + lc4 + 2] = make_float2(v.z, v.w);
    }

    // ---- K tile 0 -> Ks[0] (no readers yet; loop-top sync publishes it) ----
    const float* Kg = K + (size_t)bh * Ss * Dd;
    float4 kreg[4];
    #pragma unroll
    for (int it = 0; it < 4; it++)
        kreg[it] = *(const float4*)(Kg + (size_t)(lr + it * 16) * Dd + lc4);
    #pragma unroll
    for (int it = 0; it < 4; it++) {
        const int r = lr + it * 16;
        *(float2*)&Ks[0][r * SMS + lc4]     = make_float2(kreg[it].x, kreg[it].y);
        *(float2*)&Ks[0][r * SMS + lc4 + 2] = make_float2(kreg[it].z, kreg[it].w);
    }

    float m[4], s[4];
    #pragma unroll
    for (int i = 0; i < 4; i++) { m[i] = -3.0e38f; s[i] = 0.f; }

    const float* posg = pos + ((size_t)bh * Ss + q0) * Ss;
    float*       sg   = scr + ((size_t)bh * Ss + q0) * Ss;
    const int*   mg   = mask + b * Ss;

    int buf = 0;
    for (int k0 = 0; k0 < Ss; k0 += 64, buf ^= 1) {
        __syncthreads();   // Ks[buf] staged; iter-1 readers of Ks[buf^1] retired

        const int has_next = (k0 + 64 < Ss);
        if (has_next) {     // prefetch next K tile (overlaps GEMM)
            #pragma unroll
            for (int it = 0; it < 4; it++)
                kreg[it] = *(const float4*)
                    (Kg + (size_t)(k0 + 64 + lr + it * 16) * Dd + lc4);
        }
        // prefetch current pos / mask (coalesced 64B segments per (i,j))
        float pr[4][4];
        int mk[4];
        #pragma unroll
        for (int j = 0; j < 4; j++) mk[j] = mg[k0 + tx + 16 * j];
        #pragma unroll
        for (int i = 0; i < 4; i++) {
            const size_t rbase = (size_t)(ty + 16 * i) * Ss + k0;
            #pragma unroll
            for (int j = 0; j < 4; j++)
                pr[i][j] = posg[rbase + tx + 16 * j];
        }

        // ---- 64x64x64 GEMM on Ks[buf], f32x2 over k ----
        const float* ks = Ks[buf];
        unsigned long long acc[4][4];
        #pragma unroll
        for (int i = 0; i < 4; i++)
            #pragma unroll
            for (int j = 0; j < 4; j++) acc[i][j] = 0ull;

        #pragma unroll 8
        for (int kp = 0; kp < Dd / 2; kp++) {
            unsigned long long a2[4], b2[4];
            #pragma unroll
            for (int i = 0; i < 4; i++)
                a2[i] = *(const unsigned long long*)&Qs[(ty + 16 * i) * SMS + 2 * kp];
            #pragma unroll
            for (int j = 0; j < 4; j++)
                b2[j] = *(const unsigned long long*)&ks[(tx + 16 * j) * SMS + 2 * kp];
            #pragma unroll
            for (int i = 0; i < 4; i++)
                #pragma unroll
                for (int j = 0; j < 4; j++)
                    acc[i][j] = fma_f32x2(a2[i], b2[j], acc[i][j]);
        }

        // stage next K tile into the idle buffer (its readers retired pre-sync)
        if (has_next) {
            float* kd = Ks[buf ^ 1];
            #pragma unroll
            for (int it = 0; it < 4; it++) {
                const int r = lr + it * 16;
                *(float2*)&kd[r * SMS + lc4]     = make_float2(kreg[it].x, kreg[it].y);
                *(float2*)&kd[r * SMS + lc4 + 2] = make_float2(kreg[it].z, kreg[it].w);
            }
        }

        // ---- epilogue: +pos, *scale, mask, store raw, online (m,s) ----
        #pragma unroll
        for (int i = 0; i < 4; i++) {
            const size_t rbase = (size_t)(ty + 16 * i) * Ss + k0;
            float v[4];
            #pragma unroll
            for (int j = 0; j < 4; j++) {
                float x = (f32x2_sum(acc[i][j]) + pr[i][j]) * SCALE;
                if (mk[j] == 0) x = MASK_FILL;
                sg[rbase + tx + 16 * j] = x;
                v[j] = x;
            }
            float lm = fmaxf(fmaxf(v[0], v[1]), fmaxf(v[2], v[3]));
            float nm = fmaxf(m[i], lm);
            s[i] = s[i] * __expf(m[i] - nm)
                 + __expf(v[0] - nm) + __expf(v[1] - nm)
                 + __expf(v[2] - nm) + __expf(v[3] - nm);
            m[i] = nm;
        }
    }

    // ---- reduce (m,s) across the 16 column-lanes of each row ----
    // (the 16 lanes of a row are a contiguous, 16-aligned group in one warp)
    #pragma unroll
    for (int i = 0; i < 4; i++) {
        float mm = m[i], ss = s[i];
        #pragma unroll
        for (int off = 8; off > 0; off >>= 1) {
            float om = __shfl_xor_sync(0xffffffff, mm, off);
            float os = __shfl_xor_sync(0xffffffff, ss, off);
            float nm = fmaxf(mm, om);
            ss = ss * __expf(mm - nm) + os * __expf(om - nm);
            mm = nm;
        }
        if (tx == 0) {
            const int gr = bh * Ss + q0 + ty + 16 * i;
            g_rmax[gr] = mm;
            g_rinv[gr] = 1.0f / ss;
        }
    }
}

// ---------------------------------------------------------------------------
// Kernel 2: fused normalize + PV GEMM, double-buffered Ps/Vs (1 sync/tile).
// Reads raw scores once, writes normalized p_attn (in place: each element's
// read and write belong to the same thread), out = softmax(scores) @ V.
// Block = 64 q-rows x 64 d; k-loop in 64-chunks. grid = NROWS/64, block 256.
// ---------------------------------------------------------------------------
__global__ __launch_bounds__(256, 2)
void pv_kernel(const float* __restrict__ V,
               const float* __restrict__ scr_in,   // raw scores
               float* __restrict__ p_out,          // normalized p_attn (aliases scr_in)
               float* __restrict__ out)
{
    __shared__ float Ps[2][64 * SMS];   // [q][k] (unnormalized exp)
    __shared__ float Vs[2][64 * SMS];   // [d][k] (transposed V chunk)

    const int row0 = blockIdx.x * 64;        // global row (bh*S + q)
    const int bh   = row0 >> 11;             // S = 2048
    const int tid  = threadIdx.x;
    const int tx   = tid & 15;
    const int ty   = tid >> 4;
    const int lr   = tid >> 4;               // == ty
    const int lc4  = (tid & 15) * 4;

    // per-thread row stats (rows lr+16*it), broadcast L1 reads
    float mr[4], ir[4];
    #pragma unroll
    for (int it = 0; it < 4; it++) {
        mr[it] = g_rmax[row0 + lr + it * 16];
        ir[it] = g_rinv[row0 + lr + it * 16];
    }

    const float* Vg = V + (size_t)bh * Ss * Dd;

    // ---- tile 0: load, transform, emit p, stage into buffer 0 ----
    float4 sreg[4], vreg[4];
    #pragma unroll
    for (int it = 0; it < 4; it++) {
        sreg[it] = *(const float4*)
            (scr_in + (size_t)(row0 + lr + it * 16) * Ss + lc4);
        vreg[it] = *(const float4*)(Vg + (size_t)(lr + it * 16) * Dd + lc4);
    }
    #pragma unroll
    for (int it = 0; it < 4; it++) {
        const int r = lr + it * 16;
        float4 e;
        e.x = __expf(sreg[it].x - mr[it]);
        e.y = __expf(sreg[it].y - mr[it]);
        e.z = __expf(sreg[it].z - mr[it]);
        e.w = __expf(sreg[it].w - mr[it]);
        *(float4*)(p_out + (size_t)(row0 + r) * Ss + lc4) =
            make_float4(e.x * ir[it], e.y * ir[it], e.z * ir[it], e.w * ir[it]);
        *(float2*)&Ps[0][r * SMS + lc4]     = make_float2(e.x, e.y);
        *(float2*)&Ps[0][r * SMS + lc4 + 2] = make_float2(e.z, e.w);
        Vs[0][(lc4 + 0) * SMS + r] = vreg[it].x;
        Vs[0][(lc4 + 1) * SMS + r] = vreg[it].y;
        Vs[0][(lc4 + 2) * SMS + r] = vreg[it].z;
        Vs[0][(lc4 + 3) * SMS + r] = vreg[it].w;
    }

    unsigned long long acc[4][4];
    #pragma unroll
    for (int i = 0; i < 4; i++)
        #pragma unroll
        for (int j = 0; j < 4; j++) acc[i][j] = 0ull;

    int buf = 0;
    for (int kc = 0; kc < Ss; kc += 64, buf ^= 1) {
        __syncthreads();   // buf staged; iter-1 readers of buf^1 retired

        const int has_next = (kc + 64 < Ss);
        if (has_next) {     // prefetch next tile (overlaps GEMM)
            #pragma unroll
            for (int it = 0; it < 4; it++) {
                sreg[it] = *(const float4*)
                    (scr_in + (size_t)(row0 + lr + it * 16) * Ss + kc + 64 + lc4);
                vreg[it] = *(const float4*)
                    (Vg + (size_t)(kc + 64 + lr + it * 16) * Dd + lc4);
            }
        }

        // ---- GEMM: acc[q][d] += Ps[q][k] * Vs[d][k] on buffer `buf` ----
        const float* ps = Ps[buf];
        const float* vs = Vs[buf];
        #pragma unroll 8
        for (int kp = 0; kp < 32; kp++) {
            unsigned long long a2[4], b2[4];
            #pragma unroll
            for (int i = 0; i < 4; i++)
                a2[i] = *(const unsigned long long*)&ps[(ty + 16 * i) * SMS + 2 * kp];
            #pragma unroll
            for (int j = 0; j < 4; j++)
                b2[j] = *(const unsigned long long*)&vs[(tx + 16 * j) * SMS + 2 * kp];
            #pragma unroll
            for (int i = 0; i < 4; i++)
                #pragma unroll
                for (int j = 0; j < 4; j++)
                    acc[i][j] = fma_f32x2(a2[i], b2[j], acc[i][j]);
        }

        // ---- transform next tile, emit p, stage into buf^1 ----
        if (has_next) {
            float* pd = Ps[buf ^ 1];
            float* vd = Vs[buf ^ 1];
            #pragma unroll
            for (int it = 0; it < 4; it++) {
                const int r = lr + it * 16;
                float4 e;
                e.x = __expf(sreg[it].x - mr[it]);
                e.y = __expf(sreg[it].y - mr[it]);
                e.z = __expf(sreg[it].z - mr[it]);
                e.w = __expf(sreg[it].w - mr[it]);
                *(float4*)(p_out + (size_t)(row0 + r) * Ss + kc + 64 + lc4) =
                    make_float4(e.x * ir[it], e.y * ir[it],
                                e.z * ir[it], e.w * ir[it]);
                *(float2*)&pd[r * SMS + lc4]     = make_float2(e.x, e.y);
                *(float2*)&pd[r * SMS + lc4 + 2] = make_float2(e.z, e.w);
                vd[(lc4 + 0) * SMS + r] = vreg[it].x;
                vd[(lc4 + 1) * SMS + r] = vreg[it].y;
                vd[(lc4 + 2) * SMS + r] = vreg[it].z;
                vd[(lc4 + 3) * SMS + r] = vreg[it].w;
            }
        }
    }

    // ---- epilogue: out = acc * inv(row) (ir indexed by i: lr == ty) ----
    #pragma unroll
    for (int i = 0; i < 4; i++) {
        #pragma unroll
        for (int j = 0; j < 4; j++)
            out[(size_t)(row0 + ty + 16 * i) * Dd + tx + 16 * j] =
                f32x2_sum(acc[i][j]) * ir[i];
    }
}

// ---------------------------------------------------------------------------
extern "C" void kernel_launch(void* const* d_in, const int* in_sizes, int n_in,
                              void* d_out, int out_size)
{
    const float* Q    = (const float*)d_in[0];
    const float* K    = (const float*)d_in[1];
    const float* V    = (const float*)d_in[2];
    const float* pos  = (const float*)d_in[3];
    const int*   mask = (const int*)  d_in[4];

    float* out = (float*)d_out;

    // expected layout: [out (B,H,S,D) | p_attn (B,H,S,S)]; fall back to
    // device scratch if the harness only sized d_out for `out`.
    float* p;
    if ((size_t)out_size >= (size_t)OUT_ELEMS + P_ELEMS) {
        p = out + OUT_ELEMS;
    } else {
        cudaGetSymbolAddress((void**)&p, g_scr_fallback);
    }

    scores_stats_kernel<<<dim3(Ss / 64, Bb * Hh), 256>>>(Q, K, pos, mask, p);

    pv_kernel<<<NROWS / 64, 256>>>(V, p, p, out);
}

// round 17
// speedup vs baseline: 1.0919x; 1.0919x over previous
#include <cuda_runtime.h>
#include <cuda_bf16.h>
#include <mma.h>
#include <cstdint>
#include <math.h>

using namespace nvcuda;

// Problem constants
#define Bb 2
#define Hh 8
#define Ss 2048
#define Dd 64
#define MASK_FILL -1e9f
#define SCALE 0.08838834764831845f   // 1/sqrt(2*D)

#define OUT_ELEMS (Bb*Hh*Ss*Dd)            // 2,097,152
#define P_ELEMS   ((size_t)Bb*Hh*Ss*Ss)    // 67,108,864
#define NROWS     (Bb*Hh*Ss)               // 32,768

#define LDB 72      // bf16 leading dim: 144B rows (16B row phase shift in banks)
#define LDC 72      // f32 leading dim for C staging

// ---- scratch (__device__ globals: alloc-free rule) ----
__device__ float g_rmax[NROWS];
__device__ float g_rinv[NROWS];
__device__ float g_scr_fallback[P_ELEMS];   // used only if d_out lacks the p region

// fp32 -> bf16 hi/lo split of two values, packed bf16x2
__device__ __forceinline__ void split2(float a, float b, uint32_t& hi, uint32_t& lo)
{
    __nv_bfloat16 ah = __float2bfloat16(a), bh = __float2bfloat16(b);
    __nv_bfloat162 h, l;
    h.x = ah; h.y = bh;
    l.x = __float2bfloat16(a - __bfloat162float(ah));
    l.y = __float2bfloat16(b - __bfloat162float(bh));
    hi = *reinterpret_cast<uint32_t*>(&h);
    lo = *reinterpret_cast<uint32_t*>(&l);
}
// pack 8 floats (2 float4) -> one uint4 of hi-bf16x2 and one of lo
__device__ __forceinline__ void pack8(const float4& a, const float4& b,
                                      uint4& hi, uint4& lo)
{
    split2(a.x, a.y, hi.x, lo.x);
    split2(a.z, a.w, hi.y, lo.y);
    split2(b.x, b.y, hi.z, lo.z);
    split2(b.z, b.w, hi.w, lo.w);
}

typedef wmma::fragment<wmma::matrix_a, 16, 16, 16, __nv_bfloat16, wmma::row_major> FragA;
typedef wmma::fragment<wmma::matrix_b, 16, 16, 16, __nv_bfloat16, wmma::col_major> FragBc;
typedef wmma::fragment<wmma::matrix_b, 16, 16, 16, __nv_bfloat16, wmma::row_major> FragBr;
typedef wmma::fragment<wmma::accumulator, 16, 16, 16, float> FragC;

// dynamic smem byte offsets, kernel 1 (after 1024-align)
#define K1_QH   0
#define K1_QL   9216
#define K1_KH(b) (18432 + (b) * 18432)
#define K1_KL(b) (27648 + (b) * 18432)
#define K1_C    55296
#define K1_MASK 73728
#define K1_SIZE (81920 + 1024)

// kernel 2
#define K2_PH(b) ((b) * 18432)
#define K2_PL(b) (9216 + (b) * 18432)
#define K2_VH(b) (36864 + (b) * 18432)
#define K2_VL(b) (46080 + (b) * 18432)
#define K2_C     73728
#define K2_SIZE  (92160 + 1024)

// ===========================================================================
// Kernel 1: scores = mask((Q K^T + pos)*scale) + fused online softmax stats.
// Block = 64 q-rows of one (b,h); 32 k-tiles of 64.  8 warps.
// GEMM: WMMA bf16 3-pass (hi*hi + hi*lo + lo*hi), f32 accum.
// Warp (wr=wid>>1, wc=wid&1) owns output rows [16wr,+16), cols [32wc,+32).
// Epilogue thread role: row r4 = tid>>2, 16-col slice seg = tid&3.
// ===========================================================================
__global__ __launch_bounds__(256, 2)
void scores_wmma_kernel(const float* __restrict__ Q,
                        const float* __restrict__ K,
                        const float* __restrict__ pos,
                        const int*   __restrict__ mask,
                        float* __restrict__ scr)
{
    extern __shared__ char dsm[];
    char* base = dsm + ((1024 - ((uintptr_t)dsm & 1023)) & 1023);

    const int tid = threadIdx.x;
    const int wid = tid >> 5;
    const int bh  = blockIdx.y;
    const int b   = bh >> 3;
    const int q0  = blockIdx.x * 64;
    const int r4  = tid >> 2;
    const int seg = tid & 3;
    const int wr  = wid >> 1;
    const int wc  = wid & 1;

    int* smask = (int*)(base + K1_MASK);
    for (int i = tid; i < Ss; i += 256) smask[i] = mask[b * Ss + i];

    // ---- stage Q strip (64 x 64) as bf16 hi/lo, rows of 144B ----
    {
        const float* qrow = Q + ((size_t)bh * Ss + q0 + r4) * Dd + seg * 16;
        float4 f0 = *(const float4*)(qrow + 0);
        float4 f1 = *(const float4*)(qrow + 4);
        float4 f2 = *(const float4*)(qrow + 8);
        float4 f3 = *(const float4*)(qrow + 12);
        uint4 hA, lA, hB, lB;
        pack8(f0, f1, hA, lA);
        pack8(f2, f3, hB, lB);
        const int o = r4 * 144 + seg * 32;
        *(uint4*)(base + K1_QH + o)      = hA;
        *(uint4*)(base + K1_QH + o + 16) = hB;
        *(uint4*)(base + K1_QL + o)      = lA;
        *(uint4*)(base + K1_QL + o + 16) = lB;
    }
    // ---- stage K tile 0 ----
    {
        const float* krow = K + ((size_t)bh * Ss + r4) * Dd + seg * 16;
        float4 f0 = *(const float4*)(krow + 0);
        float4 f1 = *(const float4*)(krow + 4);
        float4 f2 = *(const float4*)(krow + 8);
        float4 f3 = *(const float4*)(krow + 12);
        uint4 hA, lA, hB, lB;
        pack8(f0, f1, hA, lA);
        pack8(f2, f3, hB, lB);
        const int o = r4 * 144 + seg * 32;
        *(uint4*)(base + K1_KH(0) + o)      = hA;
        *(uint4*)(base + K1_KH(0) + o + 16) = hB;
        *(uint4*)(base + K1_KL(0) + o)      = lA;
        *(uint4*)(base + K1_KL(0) + o + 16) = lB;
    }

    float mrun = -3.0e38f, srun = 0.f;
    const float* posg = pos + ((size_t)bh * Ss + q0 + r4) * Ss + seg * 16;
    float*       sg   = scr + ((size_t)bh * Ss + q0 + r4) * Ss + seg * 16;
    float*       C    = (float*)(base + K1_C);

    for (int t = 0; t < 32; t++) {
        const int buf = t & 1;
        __syncthreads();   // K[buf] (+Q,mask at t=0) staged; C consumed

        // prefetch next K tile into regs
        float4 kr0, kr1, kr2, kr3;
        if (t < 31) {
            const float* krow = K + ((size_t)bh * Ss + (t + 1) * 64 + r4) * Dd + seg * 16;
            kr0 = *(const float4*)(krow + 0);
            kr1 = *(const float4*)(krow + 4);
            kr2 = *(const float4*)(krow + 8);
            kr3 = *(const float4*)(krow + 12);
        }

        // ---- WMMA: 3-pass bf16 split GEMM on K[buf] ----
        FragC acc[2];
        wmma::fill_fragment(acc[0], 0.0f);
        wmma::fill_fragment(acc[1], 0.0f);
        #pragma unroll
        for (int p = 0; p < 3; p++) {
            const __nv_bfloat16* Ab = (const __nv_bfloat16*)
                (base + (p == 2 ? K1_QL : K1_QH));
            const __nv_bfloat16* Bbp = (const __nv_bfloat16*)
                (base + (p == 1 ? K1_KL(buf) : K1_KH(buf)));
            #pragma unroll
            for (int ks = 0; ks < 4; ks++) {
                FragA a;
                wmma::load_matrix_sync(a, Ab + (16 * wr) * LDB + 16 * ks, LDB);
                #pragma unroll
                for (int sub = 0; sub < 2; sub++) {
                    FragBc bf;
                    wmma::load_matrix_sync(
                        bf, Bbp + (32 * wc + 16 * sub) * LDB + 16 * ks, LDB);
                    wmma::mma_sync(acc[sub], a, bf, acc[sub]);
                }
            }
        }
        wmma::store_matrix_sync(C + (16 * wr) * LDC + 32 * wc,      acc[0], LDC, wmma::mem_row_major);
        wmma::store_matrix_sync(C + (16 * wr) * LDC + 32 * wc + 16, acc[1], LDC, wmma::mem_row_major);

        // stage next K tile into the idle buffer
        if (t < 31) {
            uint4 hA, lA, hB, lB;
            pack8(kr0, kr1, hA, lA);
            pack8(kr2, kr3, hB, lB);
            const int o = r4 * 144 + seg * 32;
            *(uint4*)(base + K1_KH(buf ^ 1) + o)      = hA;
            *(uint4*)(base + K1_KH(buf ^ 1) + o + 16) = hB;
            *(uint4*)(base + K1_KL(buf ^ 1) + o)      = lA;
            *(uint4*)(base + K1_KL(buf ^ 1) + o + 16) = lB;
        }
        __syncthreads();   // C + K[buf^1] published

        // ---- epilogue: +pos, *scale, mask -> STG raw scores; online (m,s) ----
        const float* Crow = C + r4 * LDC + seg * 16;
        const int kb = t * 64 + seg * 16;
        float x[16];
        float gmax = -3.0e38f;
        #pragma unroll
        for (int i = 0; i < 4; i++) {
            float4 cv = *(const float4*)(Crow + i * 4);
            float4 pv = *(const float4*)(posg + t * 64 + i * 4);
            float x0 = (cv.x + pv.x) * SCALE;
            float x1 = (cv.y + pv.y) * SCALE;
            float x2 = (cv.z + pv.z) * SCALE;
            float x3 = (cv.w + pv.w) * SCALE;
            if (smask[kb + i * 4 + 0] == 0) x0 = MASK_FILL;
            if (smask[kb + i * 4 + 1] == 0) x1 = MASK_FILL;
            if (smask[kb + i * 4 + 2] == 0) x2 = MASK_FILL;
            if (smask[kb + i * 4 + 3] == 0) x3 = MASK_FILL;
            *(float4*)(sg + t * 64 + i * 4) = make_float4(x0, x1, x2, x3);
            x[i * 4 + 0] = x0; x[i * 4 + 1] = x1;
            x[i * 4 + 2] = x2; x[i * 4 + 3] = x3;
            gmax = fmaxf(gmax, fmaxf(fmaxf(x0, x1), fmaxf(x2, x3)));
        }
        float nm = fmaxf(mrun, gmax);
        float acc_s = srun * __expf(mrun - nm);
        #pragma unroll
        for (int i = 0; i < 16; i++) acc_s += __expf(x[i] - nm);
        srun = acc_s;
        mrun = nm;
    }

    // reduce (m,s) across the 4 seg-lanes of each row
    #pragma unroll
    for (int off = 1; off < 4; off <<= 1) {
        float om = __shfl_xor_sync(0xffffffff, mrun, off);
        float os = __shfl_xor_sync(0xffffffff, srun, off);
        float nm = fmaxf(mrun, om);
        srun = srun * __expf(mrun - nm) + os * __expf(om - nm);
        mrun = nm;
    }
    if (seg == 0) {
        g_rmax[bh * Ss + q0 + r4] = mrun;
        g_rinv[bh * Ss + q0 + r4] = 1.0f / srun;
    }
}

// ===========================================================================
// Kernel 2: p = softmax(raw scores; stats), out = p @ V via WMMA bf16 3-pass.
// Block = 64 q-rows; 32 k-chunks of 64. Accumulators persist in registers.
// A = P[q][k] row-major; B = V[k][d] row-major.
// ===========================================================================
__global__ __launch_bounds__(256, 2)
void pv_wmma_kernel(const float* __restrict__ V,
                    const float* __restrict__ scr_in,   // raw scores
                    float* __restrict__ p_out,          // normalized p (may alias)
                    float* __restrict__ out)
{
    extern __shared__ char dsm[];
    char* base = dsm + ((1024 - ((uintptr_t)dsm & 1023)) & 1023);

    const int tid  = threadIdx.x;
    const int wid  = tid >> 5;
    const int row0 = blockIdx.x * 64;
    const int bh   = row0 >> 11;
    const int r4   = tid >> 2;
    const int seg  = tid & 3;
    const int wr   = wid >> 1;
    const int wc   = wid & 1;

    const float mr = g_rmax[row0 + r4];
    const float ir = g_rinv[row0 + r4];
    const float* srow = scr_in + (size_t)(row0 + r4) * Ss + seg * 16;
    float*       prw  = p_out  + (size_t)(row0 + r4) * Ss + seg * 16;
    const float* Vg   = V + (size_t)bh * Ss * Dd;

    // ---- stage chunk 0 ----
    {
        float4 s0 = *(const float4*)(srow + 0);
        float4 s1 = *(const float4*)(srow + 4);
        float4 s2 = *(const float4*)(srow + 8);
        float4 s3 = *(const float4*)(srow + 12);
        float4 e0, e1, e2, e3;
        e0 = make_float4(__expf(s0.x - mr), __expf(s0.y - mr), __expf(s0.z - mr), __expf(s0.w - mr));
        e1 = make_float4(__expf(s1.x - mr), __expf(s1.y - mr), __expf(s1.z - mr), __expf(s1.w - mr));
        e2 = make_float4(__expf(s2.x - mr), __expf(s2.y - mr), __expf(s2.z - mr), __expf(s2.w - mr));
        e3 = make_float4(__expf(s3.x - mr), __expf(s3.y - mr), __expf(s3.z - mr), __expf(s3.w - mr));
        *(float4*)(prw + 0)  = make_float4(e0.x * ir, e0.y * ir, e0.z * ir, e0.w * ir);
        *(float4*)(prw + 4)  = make_float4(e1.x * ir, e1.y * ir, e1.z * ir, e1.w * ir);
        *(float4*)(prw + 8)  = make_float4(e2.x * ir, e2.y * ir, e2.z * ir, e2.w * ir);
        *(float4*)(prw + 12) = make_float4(e3.x * ir, e3.y * ir, e3.z * ir, e3.w * ir);
        uint4 hA, lA, hB, lB;
        pack8(e0, e1, hA, lA);
        pack8(e2, e3, hB, lB);
        const int o = r4 * 144 + seg * 32;
        *(uint4*)(base + K2_PH(0) + o)      = hA;
        *(uint4*)(base + K2_PH(0) + o + 16) = hB;
        *(uint4*)(base + K2_PL(0) + o)      = lA;
        *(uint4*)(base + K2_PL(0) + o + 16) = lB;

        const float* vrow = Vg + (size_t)r4 * Dd + seg * 16;
        float4 v0 = *(const float4*)(vrow + 0);
        float4 v1 = *(const float4*)(vrow + 4);
        float4 v2 = *(const float4*)(vrow + 8);
        float4 v3 = *(const float4*)(vrow + 12);
        pack8(v0, v1, hA, lA);
        pack8(v2, v3, hB, lB);
        *(uint4*)(base + K2_VH(0) + o)      = hA;
        *(uint4*)(base + K2_VH(0) + o + 16) = hB;
        *(uint4*)(base + K2_VL(0) + o)      = lA;
        *(uint4*)(base + K2_VL(0) + o + 16) = lB;
    }

    FragC acc[2];
    wmma::fill_fragment(acc[0], 0.0f);
    wmma::fill_fragment(acc[1], 0.0f);

    for (int c = 0; c < 32; c++) {
        const int buf = c & 1;
        __syncthreads();   // buf staged; prior readers of buf^1 retired

        // prefetch chunk c+1 into regs
        float4 s0, s1, s2, s3, v0, v1, v2, v3;
        if (c < 31) {
            const float* sp = srow + (c + 1) * 64;
            s0 = *(const float4*)(sp + 0);
            s1 = *(const float4*)(sp + 4);
            s2 = *(const float4*)(sp + 8);
            s3 = *(const float4*)(sp + 12);
            const float* vp = Vg + (size_t)((c + 1) * 64 + r4) * Dd + seg * 16;
            v0 = *(const float4*)(vp + 0);
            v1 = *(const float4*)(vp + 4);
            v2 = *(const float4*)(vp + 8);
            v3 = *(const float4*)(vp + 12);
        }

        // ---- WMMA: acc += P[buf] @ V[buf], 3-pass split ----
        #pragma unroll
        for (int p = 0; p < 3; p++) {
            const __nv_bfloat16* Ab = (const __nv_bfloat16*)
                (base + (p == 2 ? K2_PL(buf) : K2_PH(buf)));
            const __nv_bfloat16* Bbp = (const __nv_bfloat16*)
                (base + (p == 1 ? K2_VL(buf) : K2_VH(buf)));
            #pragma unroll
            for (int ks = 0; ks < 4; ks++) {
                FragA a;
                wmma::load_matrix_sync(a, Ab + (16 * wr) * LDB + 16 * ks, LDB);
                #pragma unroll
                for (int sub = 0; sub < 2; sub++) {
                    FragBr bf;
                    wmma::load_matrix_sync(
                        bf, Bbp + (16 * ks) * LDB + 32 * wc + 16 * sub, LDB);
                    wmma::mma_sync(acc[sub], a, bf, acc[sub]);
                }
            }
        }

        // transform + stage chunk c+1 into buf^1; emit p
        if (c < 31) {
            float4 e0, e1, e2, e3;
            e0 = make_float4(__expf(s0.x - mr), __expf(s0.y - mr), __expf(s0.z - mr), __expf(s0.w - mr));
            e1 = make_float4(__expf(s1.x - mr), __expf(s1.y - mr), __expf(s1.z - mr), __expf(s1.w - mr));
            e2 = make_float4(__expf(s2.x - mr), __expf(s2.y - mr), __expf(s2.z - mr), __expf(s2.w - mr));
            e3 = make_float4(__expf(s3.x - mr), __expf(s3.y - mr), __expf(s3.z - mr), __expf(s3.w - mr));
            float* pp = prw + (c + 1) * 64;
            *(float4*)(pp + 0)  = make_float4(e0.x * ir, e0.y * ir, e0.z * ir, e0.w * ir);
            *(float4*)(pp + 4)  = make_float4(e1.x * ir, e1.y * ir, e1.z * ir, e1.w * ir);
            *(float4*)(pp + 8)  = make_float4(e2.x * ir, e2.y * ir, e2.z * ir, e2.w * ir);
            *(float4*)(pp + 12) = make_float4(e3.x * ir, e3.y * ir, e3.z * ir, e3.w * ir);
            uint4 hA, lA, hB, lB;
            const int o = r4 * 144 + seg * 32;
            pack8(e0, e1, hA, lA);
            pack8(e2, e3, hB, lB);
            *(uint4*)(base + K2_PH(buf ^ 1) + o)      = hA;
            *(uint4*)(base + K2_PH(buf ^ 1) + o + 16) = hB;
            *(uint4*)(base + K2_PL(buf ^ 1) + o)      = lA;
            *(uint4*)(base + K2_PL(buf ^ 1) + o + 16) = lB;
            pack8(v0, v1, hA, lA);
            pack8(v2, v3, hB, lB);
            *(uint4*)(base + K2_VH(buf ^ 1) + o)      = hA;
            *(uint4*)(base + K2_VH(buf ^ 1) + o + 16) = hB;
            *(uint4*)(base + K2_VL(buf ^ 1) + o)      = lA;
            *(uint4*)(base + K2_VL(buf ^ 1) + o + 16) = lB;
        }
    }

    // ---- final: acc -> C -> out * inv ----
    __syncthreads();
    float* C = (float*)(base + K2_C);
    wmma::store_matrix_sync(C + (16 * wr) * LDC + 32 * wc,      acc[0], LDC, wmma::mem_row_major);
    wmma::store_matrix_sync(C + (16 * wr) * LDC + 32 * wc + 16, acc[1], LDC, wmma::mem_row_major);
    __syncthreads();

    const float* Crow = C + r4 * LDC + seg * 16;
    float* orow = out + (size_t)(row0 + r4) * Dd + seg * 16;
    #pragma unroll
    for (int i = 0; i < 4; i++) {
        float4 cv = *(const float4*)(Crow + i * 4);
        *(float4*)(orow + i * 4) =
            make_float4(cv.x * ir, cv.y * ir, cv.z * ir, cv.w * ir);
    }
}

// ---------------------------------------------------------------------------
extern "C" void kernel_launch(void* const* d_in, const int* in_sizes, int n_in,
                              void* d_out, int out_size)
{
    const float* Q    = (const float*)d_in[0];
    const float* K    = (const float*)d_in[1];
    const float* V    = (const float*)d_in[2];
    const float* pos  = (const float*)d_in[3];
    const int*   mask = (const int*)  d_in[4];

    float* out = (float*)d_out;

    float* p;
    if ((size_t)out_size >= (size_t)OUT_ELEMS + P_ELEMS) {
        p = out + OUT_ELEMS;
    } else {
        cudaGetSymbolAddress((void**)&p, g_scr_fallback);
    }

    cudaFuncSetAttribute(scores_wmma_kernel,
                         cudaFuncAttributeMaxDynamicSharedMemorySize, K1_SIZE);
    cudaFuncSetAttribute(pv_wmma_kernel,
                         cudaFuncAttributeMaxDynamicSharedMemorySize, K2_SIZE);

    scores_wmma_kernel<<<dim3(Ss / 64, Bb * Hh), 256, K1_SIZE>>>(Q, K, pos, mask, p);

    pv_wmma_kernel<<<NROWS / 64, 256, K2_SIZE>>>(V, p, p, out);
}